// round 15
// baseline (speedup 1.0000x reference)
#include <cuda_runtime.h>
#include <cuda_bf16.h>

#define NPTS 8192
#define DIM  256
#define NSEED 5
#define NCENT 64
#define CTOT (NSEED*NCENT)   // 320
#define TOPK 8
#define NITER 20
#define STRIPE 2048

typedef unsigned long long u64;

// packed f32x2 helpers (each component is an exact IEEE fp32 FMA)
#define FMA2(d, a, b) asm("fma.rn.f32x2 %0, %1, %2, %0;" : "+l"(d) : "l"(a), "l"(b))
#define BCAST2(d, f)  asm("mov.b64 %0, {%1, %1};" : "=l"(d) : "r"(__float_as_uint(f)))
#define UNPACK2(lo, hi, v) asm("mov.b64 {%0, %1}, %2;" : "=r"(lo), "=r"(hi) : "l"(v))

// ---------------- scratch (device globals; no allocation) ----------------
__device__ float    g_simbuf[(size_t)STRIPE * NPTS];          // 64 MB stripe buffer
__device__ unsigned g_adj[(size_t)NPTS * NPTS / 32];          // 8 MB adjacency bitmap
__device__ float    g_cent[CTOT * DIM];
__device__ float    g_cnorm[CTOT];
__device__ int      g_labels[NSEED * NPTS];
__device__ int      g_tki[NPTS * TOPK];

// ---------------- adjacency bitmap ----------------
__global__ void zero_adj_kernel() {
    int i = blockIdx.x * blockDim.x + threadIdx.x;
    if (i < NPTS * NPTS / 32) g_adj[i] = 0u;
}

__global__ void scatter_adj_kernel(const int* __restrict__ ei, int E) {
    int e = blockIdx.x * blockDim.x + threadIdx.x;
    if (e >= E) return;
    unsigned r = (unsigned)ei[e];
    unsigned c = (unsigned)ei[E + e];
    unsigned code = r * (unsigned)NPTS + c;
    atomicOr(&g_adj[code >> 5], 1u << (code & 31));
}

// ---------------- kmeans: init centroids ----------------
__global__ void init_cent_kernel(const float* __restrict__ T, const int* __restrict__ init_idx) {
    int c = blockIdx.x;          // 0..319
    int t = threadIdx.x;         // 0..255 (== dim)
    int src = init_idx[c];
    float v = T[src * DIM + t];
    g_cent[c * DIM + t] = v;
    __shared__ float red[256];
    red[t] = v * v;
    __syncthreads();
    for (int s = 128; s > 0; s >>= 1) {
        if (t < s) red[t] += red[t + s];
        __syncthreads();
    }
    if (t == 0) g_cnorm[c] = red[0];
}

// ---------------- kmeans: assign (FFMA2; 128 pts x 64 cents per block) ----------------
// grid = (NPTS/128, NSEED). Same per-(pt,cent) k-ascending FFMA2 chain as all
// passing rounds -> distances & labels bitwise identical. Thread tile 8x4.
__global__ __launch_bounds__(256, 2) void assign_kernel(const float* __restrict__ T) {
    __shared__ float As[32][132];  // [k][pt 0..127]
    __shared__ float Bs[32][68];   // [k][cent 0..63]
    __shared__ float rv[128][17];
    __shared__ int   ri[128][17];

    int p0 = blockIdx.x * 128;
    int s  = blockIdx.y;           // seed
    int tid = threadIdx.x;
    int tx = tid & 15;             // cents tx*4..tx*4+3
    int ty = tid >> 4;             // pts   ty*8..ty*8+7 (4 f32x2 pairs)

    const float* C = &g_cent[(size_t)s * NCENT * DIM];
    u64 acc2[4][4] = {};           // [pt-pair 0..3][cent 0..3]
    for (int k0 = 0; k0 < DIM; k0 += 32) {
        for (int i = tid; i < 128 * 32; i += 256) {
            int rr = i >> 5, kk = i & 31;
            As[kk][rr] = T[(size_t)(p0 + rr) * DIM + k0 + kk];
        }
        for (int i = tid; i < 64 * 32; i += 256) {
            int rr = i >> 5, kk = i & 31;
            Bs[kk][rr] = C[(size_t)rr * DIM + k0 + kk];
        }
        __syncthreads();
#pragma unroll
        for (int k = 0; k < 32; k++) {
            ulonglong2 a0 = *(const ulonglong2*)&As[k][ty * 8];      // pts +0..3
            ulonglong2 a1 = *(const ulonglong2*)&As[k][ty * 8 + 4];  // pts +4..7
            float4 bv = *(const float4*)&Bs[k][tx * 4];
            u64 b0, b1, b2, b3;
            BCAST2(b0, bv.x); BCAST2(b1, bv.y); BCAST2(b2, bv.z); BCAST2(b3, bv.w);
            FMA2(acc2[0][0], a0.x, b0); FMA2(acc2[0][1], a0.x, b1);
            FMA2(acc2[0][2], a0.x, b2); FMA2(acc2[0][3], a0.x, b3);
            FMA2(acc2[1][0], a0.y, b0); FMA2(acc2[1][1], a0.y, b1);
            FMA2(acc2[1][2], a0.y, b2); FMA2(acc2[1][3], a0.y, b3);
            FMA2(acc2[2][0], a1.x, b0); FMA2(acc2[2][1], a1.x, b1);
            FMA2(acc2[2][2], a1.x, b2); FMA2(acc2[2][3], a1.x, b3);
            FMA2(acc2[3][0], a1.y, b0); FMA2(acc2[3][1], a1.y, b1);
            FMA2(acc2[3][2], a1.y, b2); FMA2(acc2[3][3], a1.y, b3);
        }
        __syncthreads();
    }
    // per-thread argmin over 4 cents for each of the 8 local pts
#pragma unroll
    for (int i = 0; i < 8; i++) {
        int p = i >> 1, comp = i & 1;
        float bvv = 3.0e38f; int bii = 0;
#pragma unroll
        for (int j = 0; j < 4; j++) {
            unsigned lo, hi;
            UNPACK2(lo, hi, acc2[p][j]);
            float dot = comp ? __uint_as_float(hi) : __uint_as_float(lo);
            int c = tx * 4 + j;
            float d = g_cnorm[s * NCENT + c] - 2.0f * dot;
            if (d < bvv) { bvv = d; bii = c; }      // ascending j: lowest idx on ties
        }
        rv[ty * 8 + i][tx] = bvv;
        ri[ty * 8 + i][tx] = bii;
    }
    __syncthreads();
    if (tid < 128) {
        float best = rv[tid][0]; int besti = ri[tid][0];
#pragma unroll
        for (int x = 1; x < 16; x++) {
            float cv = rv[tid][x]; int ci = ri[tid][x];
            if (cv < best || (cv == best && ci < besti)) { best = cv; besti = ci; }
        }
        g_labels[s * NPTS + p0 + tid] = s * NCENT + besti;   // GLOBAL centroid index
    }
}

// ---------------- kmeans: update (block per cluster, deterministic order) ----------------
__global__ __launch_bounds__(256) void update_kernel(const float* __restrict__ T) {
    int cl = blockIdx.x;            // 0..319 == GLOBAL centroid index
    int s = cl / NCENT;
    int tid = threadIdx.x;

    __shared__ int list[NPTS];      // 32 KB
    __shared__ int sc[256];
    const int* lab = &g_labels[s * NPTS];

    int my0 = tid * 32;
    int cnt = 0;
    for (int m = 0; m < 32; m++) cnt += (lab[my0 + m] == cl);

    // inclusive Hillis-Steele scan (deterministic)
    sc[tid] = cnt;
    __syncthreads();
    for (int d = 1; d < 256; d <<= 1) {
        int v = (tid >= d) ? sc[tid - d] : 0;
        __syncthreads();
        sc[tid] += v;
        __syncthreads();
    }
    int off = sc[tid] - cnt;
    int total = sc[255];
    for (int m = 0; m < 32; m++)
        if (lab[my0 + m] == cl) list[off++] = my0 + m;
    __syncthreads();

    float acc = 0.0f;
    for (int j = 0; j < total; j++)
        acc += T[(size_t)list[j] * DIM + tid];     // coalesced row reads, fixed order

    int gbase = cl * DIM + tid;
    float newv = (total > 0) ? (acc / (float)total) : g_cent[gbase];
    g_cent[gbase] = newv;

    __shared__ float red[256];
    red[tid] = newv * newv;
    __syncthreads();
    for (int q = 128; q > 0; q >>= 1) {
        if (tid < q) red[tid] += red[tid + q];
        __syncthreads();
    }
    if (tid == 0) g_cnorm[cl] = red[0];
}

// ---------------- sim GEMM (128x128 tile, f32x2 FMA, 8x8 per thread) ----------------
__global__ __launch_bounds__(256, 2) void sim_gemm_kernel(const float* __restrict__ S,
                                                          const float* __restrict__ T,
                                                          int row0) {
    __shared__ float As[32][132];   // [k][row 0..127]
    __shared__ float Bs[32][132];   // [k][col 0..127]
    int r0 = row0 + blockIdx.y * 128;
    int c0 = blockIdx.x * 128;
    int tid = threadIdx.x;
    int tx = tid & 15, ty = tid >> 4;   // cols tx*8..+7, rows ty*8..+7

    u64 acc2[4][8] = {};            // [row-pair 0..3][col 0..7]
    for (int k0 = 0; k0 < DIM; k0 += 32) {
        for (int i = tid; i < 128 * 32; i += 256) {
            int rr = i >> 5, kk = i & 31;
            As[kk][rr] = S[(size_t)(r0 + rr) * DIM + k0 + kk];
        }
        for (int i = tid; i < 128 * 32; i += 256) {
            int rr = i >> 5, kk = i & 31;
            Bs[kk][rr] = T[(size_t)(c0 + rr) * DIM + k0 + kk];
        }
        __syncthreads();
#pragma unroll
        for (int k = 0; k < 32; k++) {
            ulonglong2 a0 = *(const ulonglong2*)&As[k][ty * 8];      // rows +0..3
            ulonglong2 a1 = *(const ulonglong2*)&As[k][ty * 8 + 4];  // rows +4..7
            float4 bv0 = *(const float4*)&Bs[k][tx * 8];
            float4 bv1 = *(const float4*)&Bs[k][tx * 8 + 4];
            u64 b[8];
            BCAST2(b[0], bv0.x); BCAST2(b[1], bv0.y); BCAST2(b[2], bv0.z); BCAST2(b[3], bv0.w);
            BCAST2(b[4], bv1.x); BCAST2(b[5], bv1.y); BCAST2(b[6], bv1.z); BCAST2(b[7], bv1.w);
#pragma unroll
            for (int j = 0; j < 8; j++) {
                FMA2(acc2[0][j], a0.x, b[j]);
                FMA2(acc2[1][j], a0.y, b[j]);
                FMA2(acc2[2][j], a1.x, b[j]);
                FMA2(acc2[3][j], a1.y, b[j]);
            }
        }
        __syncthreads();
    }
#pragma unroll
    for (int i = 0; i < 8; i++) {
        int p = i >> 1, comp = i & 1;
        int gr = r0 + ty * 8 + i;
        int gc = c0 + tx * 8;
        float vals[8];
#pragma unroll
        for (int j = 0; j < 8; j++) {
            unsigned lo, hi;
            UNPACK2(lo, hi, acc2[p][j]);
            vals[j] = comp ? __uint_as_float(hi) : __uint_as_float(lo);
        }
        if (gr >= gc && gr < gc + 8) vals[gr - gc] += 10.0f;   // diagonal boost
        float* dst = &g_simbuf[(size_t)(gr - row0) * NPTS + gc];
        *(float4*)dst       = make_float4(vals[0], vals[1], vals[2], vals[3]);
        *(float4*)(dst + 4) = make_float4(vals[4], vals[5], vals[6], vals[7]);
    }
}

// ---------------- top-8 per row ----------------
__global__ __launch_bounds__(256) void topk_kernel(float* __restrict__ outD, int row0) {
    int lrow = blockIdx.x;
    int row = row0 + lrow;
    const float* srow = &g_simbuf[(size_t)lrow * NPTS];
    int tid = threadIdx.x;

    float v[32];
#pragma unroll
    for (int q = 0; q < 8; q++) {
        float4 x = *(const float4*)&srow[tid * 32 + q * 4];
        v[q * 4 + 0] = x.x; v[q * 4 + 1] = x.y; v[q * 4 + 2] = x.z; v[q * 4 + 3] = x.w;
    }
    __shared__ float sv[256];
    __shared__ int   si[256];
    int base = tid * 32;
    for (int r = 0; r < TOPK; r++) {
        float best = -3.0e38f; int bi = 0;
#pragma unroll
        for (int m = 0; m < 32; m++)
            if (v[m] > best) { best = v[m]; bi = m; }   // strict > keeps lowest col
        sv[tid] = best; si[tid] = base + bi;
        __syncthreads();
        for (int s = 128; s > 0; s >>= 1) {
            if (tid < s) {
                float ov = sv[tid + s]; int oi = si[tid + s];
                if (ov > sv[tid] || (ov == sv[tid] && oi < si[tid])) { sv[tid] = ov; si[tid] = oi; }
            }
            __syncthreads();
        }
        int wc = si[0]; float wv = sv[0];
        if (tid == 0) {
            g_tki[row * TOPK + r] = wc;
            outD[row * TOPK + r] = wv;
        }
        if ((wc >> 5) == tid) v[wc & 31] = -3.0e38f;
        __syncthreads();
    }
}

// ---------------- combine: indices + pos_mask ----------------
__global__ void combine_kernel(float* __restrict__ out) {
    int e = blockIdx.x * blockDim.x + threadIdx.x;
    if (e >= NPTS * TOPK) return;
    int i = e >> 3;
    int c = g_tki[e];
    unsigned code = (unsigned)i * (unsigned)NPTS + (unsigned)c;
    int inadj = (g_adj[code >> 5] >> (code & 31)) & 1;
    int close = 0;
#pragma unroll
    for (int s = 0; s < NSEED; s++)
        close |= (g_labels[s * NPTS + i] == g_labels[s * NPTS + c]);
    out[e] = (float)c;                               // I_knn as float
    out[NPTS * TOPK + e] = (inadj | close) ? 1.0f : 0.0f;  // pos_mask
}

// ---------------- launch ----------------
extern "C" void kernel_launch(void* const* d_in, const int* in_sizes, int n_in,
                              void* d_out, int out_size) {
    const float* student = (const float*)d_in[0];
    const float* teacher = (const float*)d_in[1];
    const int*   edge    = (const int*)d_in[2];
    const int*   kinit   = (const int*)d_in[3];
    float* out = (float*)d_out;
    int E = in_sizes[2] / 2;

    // one-time stream/event setup (host-side resources only; no device memory)
    static cudaStream_t sA = nullptr, sB = nullptr;
    static cudaEvent_t  eFork = nullptr, eA = nullptr, eB = nullptr;
    if (sA == nullptr) {
        cudaStreamCreateWithFlags(&sA, cudaStreamNonBlocking);
        cudaStreamCreateWithFlags(&sB, cudaStreamNonBlocking);
        cudaEventCreateWithFlags(&eFork, cudaEventDisableTiming);
        cudaEventCreateWithFlags(&eA, cudaEventDisableTiming);
        cudaEventCreateWithFlags(&eB, cudaEventDisableTiming);
    }

    // fork both chains off the capture (legacy) stream
    cudaEventRecord(eFork, 0);
    cudaStreamWaitEvent(sA, eFork, 0);
    cudaStreamWaitEvent(sB, eFork, 0);

    // ---- chain A: kmeans (5 seeds, one block-column per seed) ----
    dim3 agrid(NPTS / 128, NSEED);
    init_cent_kernel<<<CTOT, 256, 0, sA>>>(teacher, kinit);
    for (int it = 0; it < NITER; it++) {
        assign_kernel<<<agrid, 256, 0, sA>>>(teacher);
        update_kernel<<<CTOT, 256, 0, sA>>>(teacher);
    }
    assign_kernel<<<agrid, 256, 0, sA>>>(teacher);      // final labels

    // ---- chain B: adjacency bitmap + sim GEMM + top-k ----
    zero_adj_kernel<<<(NPTS * NPTS / 32 + 255) / 256, 256, 0, sB>>>();
    scatter_adj_kernel<<<(E + 255) / 256, 256, 0, sB>>>(edge, E);
    float* outD = out + 2 * NPTS * TOPK;
    for (int s = 0; s < NPTS / STRIPE; s++) {
        int row0 = s * STRIPE;
        dim3 grid(NPTS / 128, STRIPE / 128);
        sim_gemm_kernel<<<grid, 256, 0, sB>>>(student, teacher, row0);
        topk_kernel<<<STRIPE, 256, 0, sB>>>(outD, row0);
    }

    // join, then combine on the capture stream
    cudaEventRecord(eA, sA);
    cudaEventRecord(eB, sB);
    cudaStreamWaitEvent(0, eA, 0);
    cudaStreamWaitEvent(0, eB, 0);
    combine_kernel<<<(NPTS * TOPK + 255) / 256, 256>>>(out);
}

// round 17
// speedup vs baseline: 1.5588x; 1.5588x over previous
#include <cuda_runtime.h>
#include <cuda_bf16.h>

#define NPTS 8192
#define DIM  256
#define NSEED 5
#define NCENT 64
#define CTOT (NSEED*NCENT)   // 320
#define TOPK 8
#define NITER 20
#define STRIPE 2048

typedef unsigned long long u64;

// packed f32x2 helpers (each component is an exact IEEE fp32 FMA)
#define FMA2(d, a, b) asm("fma.rn.f32x2 %0, %1, %2, %0;" : "+l"(d) : "l"(a), "l"(b))
#define BCAST2(d, f)  asm("mov.b64 %0, {%1, %1};" : "=l"(d) : "r"(__float_as_uint(f)))
#define UNPACK2(lo, hi, v) asm("mov.b64 {%0, %1}, %2;" : "=r"(lo), "=r"(hi) : "l"(v))

// ---------------- scratch (device globals; no allocation) ----------------
__device__ float    g_simbuf[(size_t)STRIPE * NPTS];          // 64 MB stripe buffer
__device__ unsigned g_adj[(size_t)NPTS * NPTS / 32];          // 8 MB adjacency bitmap
__device__ float    g_cent[CTOT * DIM];
__device__ float    g_cnorm[CTOT];
__device__ int      g_labels[NSEED * NPTS];
__device__ int      g_tki[NPTS * TOPK];

// ---------------- adjacency bitmap ----------------
__global__ void zero_adj_kernel() {
    int i = blockIdx.x * blockDim.x + threadIdx.x;
    if (i < NPTS * NPTS / 32) g_adj[i] = 0u;
}

__global__ void scatter_adj_kernel(const int* __restrict__ ei, int E) {
    int e = blockIdx.x * blockDim.x + threadIdx.x;
    if (e >= E) return;
    unsigned r = (unsigned)ei[e];
    unsigned c = (unsigned)ei[E + e];
    unsigned code = r * (unsigned)NPTS + c;
    atomicOr(&g_adj[code >> 5], 1u << (code & 31));
}

// ---------------- kmeans: init centroids ----------------
__global__ void init_cent_kernel(const float* __restrict__ T, const int* __restrict__ init_idx) {
    int c = blockIdx.x;          // 0..319
    int t = threadIdx.x;         // 0..255 (== dim)
    int src = init_idx[c];
    float v = T[src * DIM + t];
    g_cent[c * DIM + t] = v;
    __shared__ float red[256];
    red[t] = v * v;
    __syncthreads();
    for (int s = 128; s > 0; s >>= 1) {
        if (t < s) red[t] += red[t + s];
        __syncthreads();
    }
    if (t == 0) g_cnorm[c] = red[0];
}

// ---------------- kmeans: assign (FFMA2; 64 pts x 64 cents; 64-k chunks) ----------------
// grid = (NPTS/64, NSEED). Proven R8/R14 body; only change: k-chunk 32 -> 64
// (half the barriers/load-loops). Same k-ascending FFMA2 chain -> bitwise same.
__global__ __launch_bounds__(256, 3) void assign_kernel(const float* __restrict__ T) {
    __shared__ float As[64][68];   // [k][pt]
    __shared__ float Bs[64][68];   // [k][cent]
    __shared__ float rv[64][17];
    __shared__ int   ri[64][17];

    int p0 = blockIdx.x * 64;
    int s  = blockIdx.y;           // seed
    int tid = threadIdx.x;
    int tx = tid & 15;             // cents tx*4..tx*4+3
    int ty = tid >> 4;             // pts   ty*4..ty*4+3 (2 f32x2 pairs)

    const float* C = &g_cent[(size_t)s * NCENT * DIM];
    u64 acc2[2][4] = {};           // [pt-pair][cent], zero bits == 0.0f pairs
    for (int k0 = 0; k0 < DIM; k0 += 64) {
        for (int i = tid; i < 64 * 64; i += 256) {
            int rr = i >> 6, kk = i & 63;
            As[kk][rr] = T[(size_t)(p0 + rr) * DIM + k0 + kk];
        }
        for (int i = tid; i < 64 * 64; i += 256) {
            int rr = i >> 6, kk = i & 63;
            Bs[kk][rr] = C[(size_t)rr * DIM + k0 + kk];
        }
        __syncthreads();
#pragma unroll
        for (int k = 0; k < 64; k++) {
            ulonglong2 ap = *(const ulonglong2*)&As[k][ty * 4];  // pairs (p0,p1),(p2,p3)
            float4 bv = *(const float4*)&Bs[k][tx * 4];
            u64 b0, b1, b2, b3;
            BCAST2(b0, bv.x); BCAST2(b1, bv.y); BCAST2(b2, bv.z); BCAST2(b3, bv.w);
            FMA2(acc2[0][0], ap.x, b0); FMA2(acc2[0][1], ap.x, b1);
            FMA2(acc2[0][2], ap.x, b2); FMA2(acc2[0][3], ap.x, b3);
            FMA2(acc2[1][0], ap.y, b0); FMA2(acc2[1][1], ap.y, b1);
            FMA2(acc2[1][2], ap.y, b2); FMA2(acc2[1][3], ap.y, b3);
        }
        __syncthreads();
    }
    // unpack: acc2[p][j] -> (pt ty*4+2p, pt ty*4+2p+1) with cent tx*4+j
    float dot[4][4];
#pragma unroll
    for (int p = 0; p < 2; p++)
#pragma unroll
        for (int j = 0; j < 4; j++) {
            unsigned lo, hi;
            UNPACK2(lo, hi, acc2[p][j]);
            dot[2 * p][j] = __uint_as_float(lo);
            dot[2 * p + 1][j] = __uint_as_float(hi);
        }
#pragma unroll
    for (int lp = 0; lp < 4; lp++) {
        float bv = 3.0e38f; int bi = 0;
#pragma unroll
        for (int j = 0; j < 4; j++) {
            int c = tx * 4 + j;
            float d = g_cnorm[s * NCENT + c] - 2.0f * dot[lp][j];
            if (d < bv) { bv = d; bi = c; }          // ascending j: lowest idx on ties
        }
        rv[ty * 4 + lp][tx] = bv;
        ri[ty * 4 + lp][tx] = bi;
    }
    __syncthreads();
    if (tid < 64) {
        float best = rv[tid][0]; int besti = ri[tid][0];
#pragma unroll
        for (int x = 1; x < 16; x++) {
            float cv = rv[tid][x]; int ci = ri[tid][x];
            if (cv < best || (cv == best && ci < besti)) { best = cv; besti = ci; }
        }
        g_labels[s * NPTS + p0 + tid] = s * NCENT + besti;   // GLOBAL centroid index
    }
}

// ---------------- kmeans: update (block per cluster, deterministic order) ----------------
__global__ __launch_bounds__(256) void update_kernel(const float* __restrict__ T) {
    int cl = blockIdx.x;            // 0..319 == GLOBAL centroid index
    int s = cl / NCENT;
    int tid = threadIdx.x;

    __shared__ int list[NPTS];      // 32 KB
    __shared__ int sc[256];
    const int* lab = &g_labels[s * NPTS];

    int my0 = tid * 32;
    int cnt = 0;
    for (int m = 0; m < 32; m++) cnt += (lab[my0 + m] == cl);

    // inclusive Hillis-Steele scan (deterministic)
    sc[tid] = cnt;
    __syncthreads();
    for (int d = 1; d < 256; d <<= 1) {
        int v = (tid >= d) ? sc[tid - d] : 0;
        __syncthreads();
        sc[tid] += v;
        __syncthreads();
    }
    int off = sc[tid] - cnt;
    int total = sc[255];
    for (int m = 0; m < 32; m++)
        if (lab[my0 + m] == cl) list[off++] = my0 + m;
    __syncthreads();

    float acc = 0.0f;
    for (int j = 0; j < total; j++)
        acc += T[(size_t)list[j] * DIM + tid];     // coalesced row reads, fixed order

    int gbase = cl * DIM + tid;
    float newv = (total > 0) ? (acc / (float)total) : g_cent[gbase];
    g_cent[gbase] = newv;

    __shared__ float red[256];
    red[tid] = newv * newv;
    __syncthreads();
    for (int q = 128; q > 0; q >>= 1) {
        if (tid < q) red[tid] += red[tid + q];
        __syncthreads();
    }
    if (tid == 0) g_cnorm[cl] = red[0];
}

// ---------------- sim GEMM (128x64 tile, f32x2 FMA; 64-k chunks) ----------------
__global__ __launch_bounds__(256, 2) void sim_gemm_kernel(const float* __restrict__ S,
                                                          const float* __restrict__ T,
                                                          int row0) {
    __shared__ float As[64][132];   // [k][row 0..127]
    __shared__ float Bs[64][68];    // [k][col 0..63]
    int r0 = row0 + blockIdx.y * 128;
    int c0 = blockIdx.x * 64;
    int tid = threadIdx.x;
    int tx = tid & 15, ty = tid >> 4;

    u64 acc2[4][4] = {};            // [pt-pair 0..3][cent 0..3]
    for (int k0 = 0; k0 < DIM; k0 += 64) {
        for (int i = tid; i < 128 * 64; i += 256) {
            int rr = i >> 6, kk = i & 63;
            As[kk][rr] = S[(size_t)(r0 + rr) * DIM + k0 + kk];
        }
        for (int i = tid; i < 64 * 64; i += 256) {
            int rr = i >> 6, kk = i & 63;
            Bs[kk][rr] = T[(size_t)(c0 + rr) * DIM + k0 + kk];
        }
        __syncthreads();
#pragma unroll
        for (int k = 0; k < 64; k++) {
            ulonglong2 a0 = *(const ulonglong2*)&As[k][ty * 8];      // pts +0..3
            ulonglong2 a1 = *(const ulonglong2*)&As[k][ty * 8 + 4];  // pts +4..7
            float4 bv = *(const float4*)&Bs[k][tx * 4];
            u64 b0, b1, b2, b3;
            BCAST2(b0, bv.x); BCAST2(b1, bv.y); BCAST2(b2, bv.z); BCAST2(b3, bv.w);
            FMA2(acc2[0][0], a0.x, b0); FMA2(acc2[0][1], a0.x, b1);
            FMA2(acc2[0][2], a0.x, b2); FMA2(acc2[0][3], a0.x, b3);
            FMA2(acc2[1][0], a0.y, b0); FMA2(acc2[1][1], a0.y, b1);
            FMA2(acc2[1][2], a0.y, b2); FMA2(acc2[1][3], a0.y, b3);
            FMA2(acc2[2][0], a1.x, b0); FMA2(acc2[2][1], a1.x, b1);
            FMA2(acc2[2][2], a1.x, b2); FMA2(acc2[2][3], a1.x, b3);
            FMA2(acc2[3][0], a1.y, b0); FMA2(acc2[3][1], a1.y, b1);
            FMA2(acc2[3][2], a1.y, b2); FMA2(acc2[3][3], a1.y, b3);
        }
        __syncthreads();
    }
#pragma unroll
    for (int i = 0; i < 8; i++) {
        int p = i >> 1, comp = i & 1;
        int gr = r0 + ty * 8 + i;
        int gc = c0 + tx * 4;
        float vals[4];
#pragma unroll
        for (int j = 0; j < 4; j++) {
            unsigned lo, hi;
            UNPACK2(lo, hi, acc2[p][j]);
            vals[j] = comp ? __uint_as_float(hi) : __uint_as_float(lo);
        }
        if (gr >= gc && gr < gc + 4) vals[gr - gc] += 10.0f;   // diagonal boost
        float4 v = make_float4(vals[0], vals[1], vals[2], vals[3]);
        *(float4*)&g_simbuf[(size_t)(gr - row0) * NPTS + gc] = v;
    }
}

// ---------------- top-8 per row ----------------
__global__ __launch_bounds__(256) void topk_kernel(float* __restrict__ outD, int row0) {
    int lrow = blockIdx.x;
    int row = row0 + lrow;
    const float* srow = &g_simbuf[(size_t)lrow * NPTS];
    int tid = threadIdx.x;

    float v[32];
#pragma unroll
    for (int q = 0; q < 8; q++) {
        float4 x = *(const float4*)&srow[tid * 32 + q * 4];
        v[q * 4 + 0] = x.x; v[q * 4 + 1] = x.y; v[q * 4 + 2] = x.z; v[q * 4 + 3] = x.w;
    }
    __shared__ float sv[256];
    __shared__ int   si[256];
    int base = tid * 32;
    for (int r = 0; r < TOPK; r++) {
        float best = -3.0e38f; int bi = 0;
#pragma unroll
        for (int m = 0; m < 32; m++)
            if (v[m] > best) { best = v[m]; bi = m; }   // strict > keeps lowest col
        sv[tid] = best; si[tid] = base + bi;
        __syncthreads();
        for (int s = 128; s > 0; s >>= 1) {
            if (tid < s) {
                float ov = sv[tid + s]; int oi = si[tid + s];
                if (ov > sv[tid] || (ov == sv[tid] && oi < si[tid])) { sv[tid] = ov; si[tid] = oi; }
            }
            __syncthreads();
        }
        int wc = si[0]; float wv = sv[0];
        if (tid == 0) {
            g_tki[row * TOPK + r] = wc;
            outD[row * TOPK + r] = wv;
        }
        if ((wc >> 5) == tid) v[wc & 31] = -3.0e38f;
        __syncthreads();
    }
}

// ---------------- combine: indices + pos_mask ----------------
__global__ void combine_kernel(float* __restrict__ out) {
    int e = blockIdx.x * blockDim.x + threadIdx.x;
    if (e >= NPTS * TOPK) return;
    int i = e >> 3;
    int c = g_tki[e];
    unsigned code = (unsigned)i * (unsigned)NPTS + (unsigned)c;
    int inadj = (g_adj[code >> 5] >> (code & 31)) & 1;
    int close = 0;
#pragma unroll
    for (int s = 0; s < NSEED; s++)
        close |= (g_labels[s * NPTS + i] == g_labels[s * NPTS + c]);
    out[e] = (float)c;                               // I_knn as float
    out[NPTS * TOPK + e] = (inadj | close) ? 1.0f : 0.0f;  // pos_mask
}

// ---------------- launch ----------------
extern "C" void kernel_launch(void* const* d_in, const int* in_sizes, int n_in,
                              void* d_out, int out_size) {
    const float* student = (const float*)d_in[0];
    const float* teacher = (const float*)d_in[1];
    const int*   edge    = (const int*)d_in[2];
    const int*   kinit   = (const int*)d_in[3];
    float* out = (float*)d_out;
    int E = in_sizes[2] / 2;

    // one-time stream/event setup (host-side resources only; no device memory)
    static cudaStream_t sA = nullptr, sB = nullptr;
    static cudaEvent_t  eFork = nullptr, eA = nullptr, eB = nullptr;
    if (sA == nullptr) {
        cudaStreamCreateWithFlags(&sA, cudaStreamNonBlocking);
        cudaStreamCreateWithFlags(&sB, cudaStreamNonBlocking);
        cudaEventCreateWithFlags(&eFork, cudaEventDisableTiming);
        cudaEventCreateWithFlags(&eA, cudaEventDisableTiming);
        cudaEventCreateWithFlags(&eB, cudaEventDisableTiming);
    }

    // fork both chains off the capture (legacy) stream
    cudaEventRecord(eFork, 0);
    cudaStreamWaitEvent(sA, eFork, 0);
    cudaStreamWaitEvent(sB, eFork, 0);

    // ---- chain A: kmeans (5 seeds, one block-column per seed) ----
    dim3 agrid(NPTS / 64, NSEED);
    init_cent_kernel<<<CTOT, 256, 0, sA>>>(teacher, kinit);
    for (int it = 0; it < NITER; it++) {
        assign_kernel<<<agrid, 256, 0, sA>>>(teacher);
        update_kernel<<<CTOT, 256, 0, sA>>>(teacher);
    }
    assign_kernel<<<agrid, 256, 0, sA>>>(teacher);      // final labels

    // ---- chain B: adjacency bitmap + sim GEMM + top-k ----
    zero_adj_kernel<<<(NPTS * NPTS / 32 + 255) / 256, 256, 0, sB>>>();
    scatter_adj_kernel<<<(E + 255) / 256, 256, 0, sB>>>(edge, E);
    float* outD = out + 2 * NPTS * TOPK;
    for (int s = 0; s < NPTS / STRIPE; s++) {
        int row0 = s * STRIPE;
        dim3 grid(NPTS / 64, STRIPE / 128);   // 64-wide col tiles: 128 blocks in x
        sim_gemm_kernel<<<grid, 256, 0, sB>>>(student, teacher, row0);
        topk_kernel<<<STRIPE, 256, 0, sB>>>(outD, row0);
    }

    // join, then combine on the capture stream
    cudaEventRecord(eA, sA);
    cudaEventRecord(eB, sB);
    cudaStreamWaitEvent(0, eA, 0);
    cudaStreamWaitEvent(0, eB, 0);
    combine_kernel<<<(NPTS * TOPK + 255) / 256, 256>>>(out);
}